// round 6
// baseline (speedup 1.0000x reference)
#include <cuda_runtime.h>
#include <cstdint>

// Round 5: probe the middle of the (warps x MLP) space: unroll x3 @ 5 CTAs/SM
// (40 warps, 6 outstanding LDG.128/warp = 240/SM). Two-kernel structure kept
// (graph overhead is fixed per R3/R4 evidence).
// Predict DRAM 81.9 -> 82-84%, dur 43.5 -> ~42.5us.

__global__ void rw_zero_kernel(float* out) {
    out[0] = 0.0f;
}

__device__ __forceinline__ float bce_w(float x, int h, int mid, float t) {
    float ax  = fabsf(x);
    float e   = __expf(-ax);
    float sp  = __logf(1.0f + e);             // log1p(exp(-|x|)), e in (0,1]
    float bce = fmaxf(x, 0.0f) - x * t + sp;
    return (h >= mid) ? (bce + bce) : bce;    // weight 2 or 1
}

__device__ __forceinline__ float warp_reduce(float v) {
    #pragma unroll
    for (int off = 16; off > 0; off >>= 1)
        v += __shfl_xor_sync(0xFFFFFFFF, v, off);
    return v;
}

__global__ __launch_bounds__(256, 5)
void rw_loss_kernel(const float4* __restrict__ x4,
                    const int4*  __restrict__ h4,
                    const int*   __restrict__ target_p,
                    const int*   __restrict__ H_p,
                    float*       __restrict__ out,
                    int nvec, float inv_n) {
    const float t   = (float)(*target_p);
    const int   mid = (*H_p) >> 1;

    const int stride = gridDim.x * blockDim.x;
    int i = blockIdx.x * blockDim.x + threadIdx.x;

    float acc = 0.0f;

    // Unroll x3: 6 independent 16B loads issued back-to-back.
    for (; i + 2 * stride < nvec; i += 3 * stride) {
        float4 a0 = __ldcs(&x4[i]);
        int4   b0 = h4[i];
        float4 a1 = __ldcs(&x4[i +     stride]);
        int4   b1 = h4[i +     stride];
        float4 a2 = __ldcs(&x4[i + 2 * stride]);
        int4   b2 = h4[i + 2 * stride];

        acc += bce_w(a0.x, b0.x, mid, t);
        acc += bce_w(a0.y, b0.y, mid, t);
        acc += bce_w(a0.z, b0.z, mid, t);
        acc += bce_w(a0.w, b0.w, mid, t);
        acc += bce_w(a1.x, b1.x, mid, t);
        acc += bce_w(a1.y, b1.y, mid, t);
        acc += bce_w(a1.z, b1.z, mid, t);
        acc += bce_w(a1.w, b1.w, mid, t);
        acc += bce_w(a2.x, b2.x, mid, t);
        acc += bce_w(a2.y, b2.y, mid, t);
        acc += bce_w(a2.z, b2.z, mid, t);
        acc += bce_w(a2.w, b2.w, mid, t);
    }
    // leftover: at most 2 single-stride steps per thread
    #pragma unroll 1
    for (; i < nvec; i += stride) {
        float4 a0 = __ldcs(&x4[i]);
        int4   b0 = h4[i];
        acc += bce_w(a0.x, b0.x, mid, t);
        acc += bce_w(a0.y, b0.y, mid, t);
        acc += bce_w(a0.z, b0.z, mid, t);
        acc += bce_w(a0.w, b0.w, mid, t);
    }

    // intra-block reduction
    acc = warp_reduce(acc);

    __shared__ float warp_sums[8];
    const int lane = threadIdx.x & 31;
    const int wid  = threadIdx.x >> 5;
    if (lane == 0) warp_sums[wid] = acc;
    __syncthreads();

    if (wid == 0) {
        float v = (lane < 8) ? warp_sums[lane] : 0.0f;
        #pragma unroll
        for (int off = 4; off > 0; off >>= 1)
            v += __shfl_xor_sync(0xFFFFFFFF, v, off);
        if (lane == 0)
            atomicAdd(out, v * inv_n);
    }
}

extern "C" void kernel_launch(void* const* d_in, const int* in_sizes, int n_in,
                              void* d_out, int out_size) {
    const float* x      = (const float*)d_in[0];   // logits, N fp32
    const int*   target = (const int*)d_in[1];     // scalar int
    const int*   hidx   = (const int*)d_in[2];     // height_indices, N int32
    const int*   Hp     = (const int*)d_in[3];     // scalar int
    float* out = (float*)d_out;

    const int n = in_sizes[0];
    const int nvec = n / 4;   // N divisible by 4
    const float inv_n = 1.0f / (float)n;

    rw_zero_kernel<<<1, 1>>>(out);

    const int threads = 256;
    const int blocks  = 740;  // 148 SMs * 5
    rw_loss_kernel<<<blocks, threads>>>(
        (const float4*)x, (const int4*)hidx, target, Hp, out, nvec, inv_n);
}

// round 7
// speedup vs baseline: 1.0307x; 1.0307x over previous
#include <cuda_runtime.h>
#include <cstdint>

// Round 6: lock in the measured optimum (R1 config). Config sweep complete:
// 48 warps/SM x 4 outstanding LDG.128, __ldcs on both streams is the peak
// (81.9% DRAM, 6.49 TB/s). All neighboring configs (more occ, more MLP,
// fusion) regress 1-3%. Predict dur ~43.5us.

__global__ void rw_zero_kernel(float* out) {
    out[0] = 0.0f;
}

__device__ __forceinline__ float bce_w(float x, int h, int mid, float t) {
    float ax  = fabsf(x);
    float e   = __expf(-ax);
    float sp  = __logf(1.0f + e);             // log1p(exp(-|x|)), e in (0,1]
    float bce = fmaxf(x, 0.0f) - x * t + sp;
    return (h >= mid) ? (bce + bce) : bce;    // weight 2 or 1
}

__global__ __launch_bounds__(256, 6)
void rw_loss_kernel(const float4* __restrict__ x4,
                    const int4*  __restrict__ h4,
                    const int*   __restrict__ target_p,
                    const int*   __restrict__ H_p,
                    float*       __restrict__ out,
                    int nvec, float inv_n) {
    const float t   = (float)(*target_p);
    const int   mid = (*H_p) >> 1;

    const int stride = gridDim.x * blockDim.x;
    int i = blockIdx.x * blockDim.x + threadIdx.x;

    float acc = 0.0f;

    // Unroll x2: 4 independent 16B loads issued back-to-back -> deep MLP.
    for (; i + stride < nvec; i += 2 * stride) {
        float4 a0 = __ldcs(&x4[i]);
        int4   b0 = __ldcs(&h4[i]);
        float4 a1 = __ldcs(&x4[i + stride]);
        int4   b1 = __ldcs(&h4[i + stride]);

        acc += bce_w(a0.x, b0.x, mid, t);
        acc += bce_w(a0.y, b0.y, mid, t);
        acc += bce_w(a0.z, b0.z, mid, t);
        acc += bce_w(a0.w, b0.w, mid, t);
        acc += bce_w(a1.x, b1.x, mid, t);
        acc += bce_w(a1.y, b1.y, mid, t);
        acc += bce_w(a1.z, b1.z, mid, t);
        acc += bce_w(a1.w, b1.w, mid, t);
    }
    if (i < nvec) {  // at most one leftover per thread
        float4 a0 = __ldcs(&x4[i]);
        int4   b0 = __ldcs(&h4[i]);
        acc += bce_w(a0.x, b0.x, mid, t);
        acc += bce_w(a0.y, b0.y, mid, t);
        acc += bce_w(a0.z, b0.z, mid, t);
        acc += bce_w(a0.w, b0.w, mid, t);
    }

    // warp reduction
    #pragma unroll
    for (int off = 16; off > 0; off >>= 1)
        acc += __shfl_xor_sync(0xFFFFFFFF, acc, off);

    __shared__ float warp_sums[8];
    const int lane = threadIdx.x & 31;
    const int wid  = threadIdx.x >> 5;
    if (lane == 0) warp_sums[wid] = acc;
    __syncthreads();

    if (wid == 0) {
        float v = (lane < 8) ? warp_sums[lane] : 0.0f;
        #pragma unroll
        for (int off = 4; off > 0; off >>= 1)
            v += __shfl_xor_sync(0xFFFFFFFF, v, off);
        if (lane == 0)
            atomicAdd(out, v * inv_n);
    }
}

extern "C" void kernel_launch(void* const* d_in, const int* in_sizes, int n_in,
                              void* d_out, int out_size) {
    const float* x      = (const float*)d_in[0];   // logits, N fp32
    const int*   target = (const int*)d_in[1];     // scalar int
    const int*   hidx   = (const int*)d_in[2];     // height_indices, N int32
    const int*   Hp     = (const int*)d_in[3];     // scalar int
    float* out = (float*)d_out;

    const int n = in_sizes[0];
    const int nvec = n / 4;   // N divisible by 4
    const float inv_n = 1.0f / (float)n;

    rw_zero_kernel<<<1, 1>>>(out);

    const int threads = 256;
    const int blocks  = 888;  // 148 SMs * 6
    rw_loss_kernel<<<blocks, threads>>>(
        (const float4*)x, (const int4*)hidx, target, Hp, out, nvec, inv_n);
}